// round 1
// baseline (speedup 1.0000x reference)
#include <cuda_runtime.h>

#define N_MAX 50000
#define E_MAX 800000

// Scratch (device globals; allocation-free rule)
__device__ __align__(16) float g_acc1[N_MAX * 8];    // per node: s1[3], deg, eagg[3], pad
__device__ __align__(16) float g_h1[N_MAX * 128];
__device__ __align__(16) float g_aj2[N_MAX * 64];
__device__ __align__(16) float g_acc2[N_MAX * 64];
__device__ __align__(16) float g_aj3[N_MAX * 32];
__device__ __align__(16) float g_acc3[N_MAX * 32];

// Transposed / packed weights
__device__ float g_W1t[10 * 128];                    // rows: Wi(3), Wj(3), We(3), b
__device__ __align__(16) float g_W2it[128 * 64];     // packed: [(k>>2)*256 + o*4 + (k&3)]
__device__ __align__(16) float g_W2jt[128 * 64];
__device__ float g_W2eb[4 * 64];                     // rows: We(3), b
__device__ __align__(16) float g_W3it[64 * 32];
__device__ __align__(16) float g_W3jt[64 * 32];
__device__ float g_W3eb[4 * 32];

__global__ void k_prep(const float* __restrict__ W1, const float* __restrict__ b1,
                       const float* __restrict__ W2, const float* __restrict__ b2,
                       const float* __restrict__ W3, const float* __restrict__ b3) {
    int idx = blockIdx.x * blockDim.x + threadIdx.x;
    if (idx < 1280) {                                 // W1t
        int k = idx / 128, o = idx % 128;
        g_W1t[idx] = (k < 9) ? W1[o * 9 + k] : b1[o];
        return;
    }
    idx -= 1280;
    if (idx < 8192) {                                 // W2i transposed+packed
        int k = idx / 64, o = idx % 64;
        g_W2it[(k >> 2) * 256 + o * 4 + (k & 3)] = W2[o * 259 + k];
        return;
    }
    idx -= 8192;
    if (idx < 8192) {                                 // W2j
        int k = idx / 64, o = idx % 64;
        g_W2jt[(k >> 2) * 256 + o * 4 + (k & 3)] = W2[o * 259 + 128 + k];
        return;
    }
    idx -= 8192;
    if (idx < 256) {                                  // W2e + b2
        int k = idx / 64, o = idx % 64;
        g_W2eb[idx] = (k < 3) ? W2[o * 259 + 256 + k] : b2[o];
        return;
    }
    idx -= 256;
    if (idx < 2048) {                                 // W3i
        int k = idx / 32, o = idx % 32;
        g_W3it[(k >> 2) * 128 + o * 4 + (k & 3)] = W3[o * 131 + k];
        return;
    }
    idx -= 2048;
    if (idx < 2048) {                                 // W3j
        int k = idx / 32, o = idx % 32;
        g_W3jt[(k >> 2) * 128 + o * 4 + (k & 3)] = W3[o * 131 + 64 + k];
        return;
    }
    idx -= 2048;
    if (idx < 128) {                                  // W3e + b3
        int k = idx / 32, o = idx % 32;
        g_W3eb[idx] = (k < 3) ? W3[o * 131 + 128 + k] : b3[o];
    }
}

// Init per-node accumulators with self-loop contribution: s1 = x[i], deg = 1, eagg = 0
__global__ void k_init(const float* __restrict__ x, int n) {
    int i = blockIdx.x * blockDim.x + threadIdx.x;
    if (i >= n) return;
    float4* a = (float4*)g_acc1;
    a[i * 2]     = make_float4(x[i * 3], x[i * 3 + 1], x[i * 3 + 2], 1.0f);
    a[i * 2 + 1] = make_float4(0.f, 0.f, 0.f, 0.f);
}

// Per real edge: accumulate x[src] (layer-1 aggregation in input space), deg, eagg
__global__ void k_edge1(const int* __restrict__ ei, const float* __restrict__ ea,
                        const float* __restrict__ x, int e) {
    int t = blockIdx.x * blockDim.x + threadIdx.x;
    if (t >= e) return;
    int s = ei[t], d = ei[e + t];
    float4* a = (float4*)g_acc1;
    atomicAdd(&a[d * 2],     make_float4(x[s * 3], x[s * 3 + 1], x[s * 3 + 2], 1.0f));
    atomicAdd(&a[d * 2 + 1], make_float4(ea[t * 3], ea[t * 3 + 1], ea[t * 3 + 2], 0.0f));
}

// Layer 1: h1 = relu( deg*(x@Wi.T + b) + s1@Wj.T + eagg@We.T )
__global__ void k_layer1(const float* __restrict__ x, int n) {
    int i = blockIdx.x;
    int o = threadIdx.x;                              // 128 threads
    __shared__ float m[8];
    __shared__ float sx[3];
    if (o < 8) m[o] = g_acc1[i * 8 + o];
    else if (o < 11) sx[o - 8] = x[i * 3 + (o - 8)];
    __syncthreads();
    float ai = g_W1t[9 * 128 + o];                    // b
    ai += sx[0] * g_W1t[0 * 128 + o] + sx[1] * g_W1t[1 * 128 + o] + sx[2] * g_W1t[2 * 128 + o];
    float r = m[3] * ai;
    r += m[0] * g_W1t[3 * 128 + o] + m[1] * g_W1t[4 * 128 + o] + m[2] * g_W1t[5 * 128 + o];
    r += m[4] * g_W1t[6 * 128 + o] + m[5] * g_W1t[7 * 128 + o] + m[6] * g_W1t[8 * 128 + o];
    g_h1[i * 128 + o] = fmaxf(r, 0.0f);
}

// Layer 2 transform: per node compute ai2, aj2 (128->64); init acc2 with non-scatter terms
__global__ void k_layer2a(int n) {
    int half = threadIdx.x >> 6;                      // 2 nodes per 128-thread block
    int o = threadIdx.x & 63;
    int i = blockIdx.x * 2 + half;
    __shared__ float hs[2][128];
    __shared__ float mm[2][8];
    if (i < n) {
        hs[half][o]      = g_h1[i * 128 + o];
        hs[half][o + 64] = g_h1[i * 128 + 64 + o];
        if (o < 8) mm[half][o] = g_acc1[i * 8 + o];
    }
    __syncthreads();
    if (i >= n) return;
    float ai = 0.f, aj = 0.f;
    const float4* Wi = (const float4*)g_W2it;
    const float4* Wj = (const float4*)g_W2jt;
#pragma unroll 8
    for (int k4 = 0; k4 < 32; k4++) {
        float4 wi = Wi[k4 * 64 + o];
        float4 wj = Wj[k4 * 64 + o];
        float h0 = hs[half][4 * k4], h1v = hs[half][4 * k4 + 1];
        float h2v = hs[half][4 * k4 + 2], h3v = hs[half][4 * k4 + 3];
        ai += h0 * wi.x + h1v * wi.y + h2v * wi.z + h3v * wi.w;
        aj += h0 * wj.x + h1v * wj.y + h2v * wj.z + h3v * wj.w;
    }
    float deg = mm[half][3];
    float c = deg * (ai + g_W2eb[192 + o]) + aj;      // deg*(ai+b) + self-loop aj
    c += mm[half][4] * g_W2eb[o] + mm[half][5] * g_W2eb[64 + o] + mm[half][6] * g_W2eb[128 + o];
    g_acc2[i * 64 + o] = c;
    g_aj2[i * 64 + o] = aj;
}

// Layer 2 scatter: acc2[dst] += aj2[src], 16 float4 atomics per edge
__global__ void k_scatter2(const int* __restrict__ ei, int e) {
    int t = blockIdx.x * blockDim.x + threadIdx.x;
    if (t >= e * 16) return;
    int eidx = t >> 4;
    int c = t & 15;
    int s = ei[eidx], d = ei[e + eidx];
    float4 v = ((const float4*)g_aj2)[s * 16 + c];
    atomicAdd(((float4*)g_acc2) + d * 16 + c, v);
}

// Layer 3 transform: h2 = relu(acc2); compute ai3, aj3 (64->32); init acc3
__global__ void k_layer3a(int n) {
    int q = threadIdx.x >> 5;                         // 4 nodes per 128-thread block
    int o = threadIdx.x & 31;
    int i = blockIdx.x * 4 + q;
    __shared__ float hs[4][64];
    __shared__ float mm[4][8];
    if (i < n) {
        hs[q][o]      = fmaxf(g_acc2[i * 64 + o], 0.f);
        hs[q][o + 32] = fmaxf(g_acc2[i * 64 + 32 + o], 0.f);
        if (o < 8) mm[q][o] = g_acc1[i * 8 + o];
    }
    __syncthreads();
    if (i >= n) return;
    float ai = 0.f, aj = 0.f;
    const float4* Wi = (const float4*)g_W3it;
    const float4* Wj = (const float4*)g_W3jt;
#pragma unroll 8
    for (int k4 = 0; k4 < 16; k4++) {
        float4 wi = Wi[k4 * 32 + o];
        float4 wj = Wj[k4 * 32 + o];
        float h0 = hs[q][4 * k4], h1v = hs[q][4 * k4 + 1];
        float h2v = hs[q][4 * k4 + 2], h3v = hs[q][4 * k4 + 3];
        ai += h0 * wi.x + h1v * wi.y + h2v * wi.z + h3v * wi.w;
        aj += h0 * wj.x + h1v * wj.y + h2v * wj.z + h3v * wj.w;
    }
    float deg = mm[q][3];
    float c = deg * (ai + g_W3eb[96 + o]) + aj;
    c += mm[q][4] * g_W3eb[o] + mm[q][5] * g_W3eb[32 + o] + mm[q][6] * g_W3eb[64 + o];
    g_acc3[i * 32 + o] = c;
    g_aj3[i * 32 + o] = aj;
}

// Layer 3 scatter: acc3[dst] += aj3[src], 8 float4 atomics per edge
__global__ void k_scatter3(const int* __restrict__ ei, int e) {
    int t = blockIdx.x * blockDim.x + threadIdx.x;
    if (t >= e * 8) return;
    int eidx = t >> 3;
    int c = t & 7;
    int s = ei[eidx], d = ei[e + eidx];
    float4 v = ((const float4*)g_aj3)[s * 8 + c];
    atomicAdd(((float4*)g_acc3) + d * 8 + c, v);
}

// Classifier + log_softmax: one warp per node
__global__ void k_final(const float* __restrict__ Wc, const float* __restrict__ bc,
                        float* __restrict__ out, int n) {
    int lane = threadIdx.x & 31;
    int w = threadIdx.x >> 5;
    int i = blockIdx.x * 8 + w;
    if (i >= n) return;
    float h = g_acc3[i * 32 + lane];
    float l[4];
#pragma unroll
    for (int c = 0; c < 4; c++) {
        float v = h * Wc[c * 32 + lane];
#pragma unroll
        for (int off = 16; off; off >>= 1) v += __shfl_xor_sync(0xffffffff, v, off);
        l[c] = v + bc[c];
    }
    float mx = fmaxf(fmaxf(l[0], l[1]), fmaxf(l[2], l[3]));
    float se = expf(l[0] - mx) + expf(l[1] - mx) + expf(l[2] - mx) + expf(l[3] - mx);
    float lse = mx + logf(se);
    if (lane < 4) out[i * 4 + lane] = l[lane] - lse;
}

extern "C" void kernel_launch(void* const* d_in, const int* in_sizes, int n_in,
                              void* d_out, int out_size) {
    const float* x  = (const float*)d_in[0];
    const int*   ei = (const int*)d_in[1];
    const float* ea = (const float*)d_in[2];
    const float* W1 = (const float*)d_in[3];
    const float* b1 = (const float*)d_in[4];
    const float* W2 = (const float*)d_in[5];
    const float* b2 = (const float*)d_in[6];
    const float* W3 = (const float*)d_in[7];
    const float* b3 = (const float*)d_in[8];
    const float* Wc = (const float*)d_in[9];
    const float* bc = (const float*)d_in[10];
    float* out = (float*)d_out;
    int n = in_sizes[0] / 3;
    int e = in_sizes[1] / 2;

    k_prep<<<87, 256>>>(W1, b1, W2, b2, W3, b3);
    k_init<<<(n + 255) / 256, 256>>>(x, n);
    k_edge1<<<(e + 255) / 256, 256>>>(ei, ea, x, e);
    k_layer1<<<n, 128>>>(x, n);
    k_layer2a<<<(n + 1) / 2, 128>>>(n);
    k_scatter2<<<(e * 16 + 255) / 256, 256>>>(ei, e);
    k_layer3a<<<(n + 3) / 4, 128>>>(n);
    k_scatter3<<<(e * 8 + 255) / 256, 256>>>(ei, e);
    k_final<<<(n + 7) / 8, 256>>>(Wc, bc, out, n);
}

// round 4
// speedup vs baseline: 1.6473x; 1.6473x over previous
#include <cuda_runtime.h>

#define N_MAX 50000
#define E_MAX 800000

// ---------------- scratch (device globals; allocation-free rule) ----------------
__device__ __align__(16) float g_acc1[N_MAX * 8];    // per node: s1[3], deg, eagg[3], pad
__device__ __align__(16) float g_aj2[N_MAX * 64];
__device__ __align__(16) float g_c2[N_MAX * 64];     // layer2 non-scatter part
__device__ __align__(16) float g_aj3[N_MAX * 32];
__device__ __align__(16) float g_c3[N_MAX * 32];     // layer3 non-scatter part

// CSR (built per call)
__device__ int  g_cnt[N_MAX];
__device__ int  g_off[N_MAX + 1];
__device__ int  g_cur[N_MAX];
__device__ int  g_part[256];
__device__ int2 g_csr[E_MAX];                        // (src, edge_id) sorted by dst

// Transposed / packed weights
__device__ float g_W1t[10 * 128];                    // rows: Wi(3), Wj(3), We(3), b
__device__ __align__(16) float g_W2it[128 * 64];     // packed: [(k>>2)*256 + o*4 + (k&3)]
__device__ __align__(16) float g_W2jt[128 * 64];
__device__ float g_W2eb[4 * 64];                     // rows: We(3), b
__device__ __align__(16) float g_W3it[64 * 32];
__device__ __align__(16) float g_W3jt[64 * 32];
__device__ float g_W3eb[4 * 32];

// ---------------- weight prep ----------------
__global__ void k_prep(const float* __restrict__ W1, const float* __restrict__ b1,
                       const float* __restrict__ W2, const float* __restrict__ b2,
                       const float* __restrict__ W3, const float* __restrict__ b3) {
    int idx = blockIdx.x * blockDim.x + threadIdx.x;
    if (idx < 1280) {
        int k = idx / 128, o = idx % 128;
        g_W1t[idx] = (k < 9) ? W1[o * 9 + k] : b1[o];
        return;
    }
    idx -= 1280;
    if (idx < 8192) {
        int k = idx / 64, o = idx % 64;
        g_W2it[(k >> 2) * 256 + o * 4 + (k & 3)] = W2[o * 259 + k];
        return;
    }
    idx -= 8192;
    if (idx < 8192) {
        int k = idx / 64, o = idx % 64;
        g_W2jt[(k >> 2) * 256 + o * 4 + (k & 3)] = W2[o * 259 + 128 + k];
        return;
    }
    idx -= 8192;
    if (idx < 256) {
        int k = idx / 64, o = idx % 64;
        g_W2eb[idx] = (k < 3) ? W2[o * 259 + 256 + k] : b2[o];
        return;
    }
    idx -= 256;
    if (idx < 2048) {
        int k = idx / 32, o = idx % 32;
        g_W3it[(k >> 2) * 128 + o * 4 + (k & 3)] = W3[o * 131 + k];
        return;
    }
    idx -= 2048;
    if (idx < 2048) {
        int k = idx / 32, o = idx % 32;
        g_W3jt[(k >> 2) * 128 + o * 4 + (k & 3)] = W3[o * 131 + 64 + k];
        return;
    }
    idx -= 2048;
    if (idx < 128) {
        int k = idx / 32, o = idx % 32;
        g_W3eb[idx] = (k < 3) ? W3[o * 131 + 128 + k] : b3[o];
    }
}

// ---------------- CSR build ----------------
__global__ void k_zero(int n) {
    int i = blockIdx.x * blockDim.x + threadIdx.x;
    if (i < n) g_cnt[i] = 0;
}

__global__ void k_count(const int* __restrict__ ei, int e) {
    int t = blockIdx.x * blockDim.x + threadIdx.x;
    if (t < e) atomicAdd(&g_cnt[ei[e + t]], 1);
}

__global__ void k_scan1(int n) {
    __shared__ int sd[512];
    int tid = threadIdx.x;
    int i = blockIdx.x * 512 + tid;
    int v = (i < n) ? g_cnt[i] : 0;
    sd[tid] = v;
    __syncthreads();
    for (int of = 1; of < 512; of <<= 1) {
        int t = (tid >= of) ? sd[tid - of] : 0;
        __syncthreads();
        sd[tid] += t;
        __syncthreads();
    }
    if (i < n) g_off[i + 1] = sd[tid];               // block-local inclusive
    if (tid == 511) g_part[blockIdx.x] = sd[511];
}

__global__ void k_scan2(int nb) {
    __shared__ int sd[256];
    int tid = threadIdx.x;
    int v = (tid < nb) ? g_part[tid] : 0;
    sd[tid] = v;
    __syncthreads();
    for (int of = 1; of < 256; of <<= 1) {
        int t = (tid >= of) ? sd[tid - of] : 0;
        __syncthreads();
        sd[tid] += t;
        __syncthreads();
    }
    if (tid < nb) g_part[tid] = sd[tid] - v;         // exclusive
}

__global__ void k_scan3(int n) {
    int i = blockIdx.x * blockDim.x + threadIdx.x;
    if (i >= n) return;
    int fin = g_off[i + 1] + g_part[i >> 9];
    g_off[i + 1] = fin;
    g_cur[i] = fin - g_cnt[i];                       // start offset for node i
    if (i == 0) g_off[0] = 0;
}

__global__ void k_fill(const int* __restrict__ ei, int e) {
    int t = blockIdx.x * blockDim.x + threadIdx.x;
    if (t >= e) return;
    int s = ei[t], d = ei[e + t];
    int pos = atomicAdd(&g_cur[d], 1);
    g_csr[pos] = make_int2(s, t);
}

// ---------------- layer-1 aggregation (gather): s1, deg, eagg per node ----------------
__global__ void k_agg1(const float* __restrict__ x, const float* __restrict__ ea, int n) {
    int i = blockIdx.x * blockDim.x + threadIdx.x;
    if (i >= n) return;
    int beg = g_off[i], end = g_off[i + 1];
    float s0 = x[i * 3], s1 = x[i * 3 + 1], s2 = x[i * 3 + 2];   // self loop
    float e0 = 0.f, e1 = 0.f, e2 = 0.f;
    for (int j = beg; j < end; j++) {
        int2 se = g_csr[j];
        s0 += x[se.x * 3];
        s1 += x[se.x * 3 + 1];
        s2 += x[se.x * 3 + 2];
        e0 += ea[se.y * 3];
        e1 += ea[se.y * 3 + 1];
        e2 += ea[se.y * 3 + 2];
    }
    float4* a = (float4*)g_acc1;
    a[i * 2]     = make_float4(s0, s1, s2, (float)(end - beg + 1));
    a[i * 2 + 1] = make_float4(e0, e1, e2, 0.f);
}

// ---------------- fused layer1 + layer2 transform: h1 (smem) -> ai2/aj2/c2 ----------------
__global__ void k_l12(const float* __restrict__ x, int n) {
    __shared__ float mm[2][8];
    __shared__ float sx[2][3];
    __shared__ float hs[2][128];
    int t = threadIdx.x;
    int half = t >> 6, o = t & 63;
    int i = blockIdx.x * 2 + half;

    if (t < 16) {
        int nd = t >> 3, c = t & 7;
        int ii = blockIdx.x * 2 + nd;
        if (ii < n) mm[nd][c] = g_acc1[ii * 8 + c];
    } else if (t < 22) {
        int nd = (t - 16) / 3, c = (t - 16) % 3;
        int ii = blockIdx.x * 2 + nd;
        if (ii < n) sx[nd][c] = x[ii * 3 + c];
    }
    __syncthreads();

    // h1 phase: each thread computes 2 of its node's 128 outputs
    if (i < n) {
#pragma unroll
        for (int p = 0; p < 2; p++) {
            int oo = o + p * 64;
            float ai = g_W1t[9 * 128 + oo];
            ai += sx[half][0] * g_W1t[0 * 128 + oo] + sx[half][1] * g_W1t[1 * 128 + oo]
                + sx[half][2] * g_W1t[2 * 128 + oo];
            float r = mm[half][3] * ai;
            r += mm[half][0] * g_W1t[3 * 128 + oo] + mm[half][1] * g_W1t[4 * 128 + oo]
               + mm[half][2] * g_W1t[5 * 128 + oo];
            r += mm[half][4] * g_W1t[6 * 128 + oo] + mm[half][5] * g_W1t[7 * 128 + oo]
               + mm[half][6] * g_W1t[8 * 128 + oo];
            hs[half][oo] = fmaxf(r, 0.0f);
        }
    }
    __syncthreads();
    if (i >= n) return;

    float ai = 0.f, aj = 0.f;
    const float4* Wi = (const float4*)g_W2it;
    const float4* Wj = (const float4*)g_W2jt;
#pragma unroll 8
    for (int k4 = 0; k4 < 32; k4++) {
        float4 wi = Wi[k4 * 64 + o];
        float4 wj = Wj[k4 * 64 + o];
        float h0 = hs[half][4 * k4], h1v = hs[half][4 * k4 + 1];
        float h2v = hs[half][4 * k4 + 2], h3v = hs[half][4 * k4 + 3];
        ai += h0 * wi.x + h1v * wi.y + h2v * wi.z + h3v * wi.w;
        aj += h0 * wj.x + h1v * wj.y + h2v * wj.z + h3v * wj.w;
    }
    float deg = mm[half][3];
    float c = deg * (ai + g_W2eb[192 + o]) + aj;     // deg*(ai+b2) + self-loop aj
    c += mm[half][4] * g_W2eb[o] + mm[half][5] * g_W2eb[64 + o] + mm[half][6] * g_W2eb[128 + o];
    g_c2[i * 64 + o] = c;
    g_aj2[i * 64 + o] = aj;
}

// ---------------- fused layer2 aggregation + layer3 transform (block per node) ----------------
__global__ void __launch_bounds__(64) k_l23(int n) {
    __shared__ float hs[64];
    __shared__ float mm8[8];
    __shared__ float ajs[32];
    __shared__ int rng[2];
    int i = blockIdx.x;
    int o = threadIdx.x;                             // 64 threads

    if (o < 8) mm8[o] = g_acc1[i * 8 + o];
    if (o >= 8 && o < 10) rng[o - 8] = g_off[i + (o - 8)];
    float acc = g_c2[i * 64 + o];
    __syncthreads();

    int beg = rng[0], end = rng[1];
    for (int j = beg; j < end; j++) {
        int s = g_csr[j].x;                          // warp-uniform broadcast
        acc += g_aj2[s * 64 + o];                    // coalesced 256B row
    }
    hs[o] = fmaxf(acc, 0.0f);
    __syncthreads();

    // transform: warp 0 computes ai3[0..31], warp 1 computes aj3[0..31]
    int oo = o & 31;
    const float4* W = (o < 32) ? (const float4*)g_W3it : (const float4*)g_W3jt;
    float a = 0.f;
#pragma unroll 8
    for (int k4 = 0; k4 < 16; k4++) {
        float4 w = W[k4 * 32 + oo];
        a += hs[4 * k4] * w.x + hs[4 * k4 + 1] * w.y + hs[4 * k4 + 2] * w.z + hs[4 * k4 + 3] * w.w;
    }
    if (o >= 32) {
        ajs[oo] = a;
        g_aj3[i * 32 + oo] = a;
    }
    __syncthreads();
    if (o < 32) {
        float deg = mm8[3];
        float c = deg * (a + g_W3eb[96 + oo]) + ajs[oo];
        c += mm8[4] * g_W3eb[oo] + mm8[5] * g_W3eb[32 + oo] + mm8[6] * g_W3eb[64 + oo];
        g_c3[i * 32 + oo] = c;
    }
}

// ---------------- fused layer3 aggregation + classifier + log_softmax (warp per node) ----------------
__global__ void k_l3f(const float* __restrict__ Wc, const float* __restrict__ bc,
                      float* __restrict__ out, int n) {
    int lane = threadIdx.x & 31;
    int w = threadIdx.x >> 5;
    int i = blockIdx.x * 8 + w;
    if (i >= n) return;

    int beg = g_off[i], end = g_off[i + 1];
    float h = g_c3[i * 32 + lane];
    for (int j = beg; j < end; j++) {
        int s = g_csr[j].x;                          // warp-uniform broadcast
        h += g_aj3[s * 32 + lane];                   // coalesced 128B row
    }

    float l[4];
#pragma unroll
    for (int c = 0; c < 4; c++) {
        float v = h * Wc[c * 32 + lane];
#pragma unroll
        for (int off = 16; off; off >>= 1) v += __shfl_xor_sync(0xffffffff, v, off);
        l[c] = v + bc[c];
    }
    float mx = fmaxf(fmaxf(l[0], l[1]), fmaxf(l[2], l[3]));
    float se = expf(l[0] - mx) + expf(l[1] - mx) + expf(l[2] - mx) + expf(l[3] - mx);
    float lse = mx + logf(se);
    if (lane < 4) out[i * 4 + lane] = l[lane] - lse;
}

extern "C" void kernel_launch(void* const* d_in, const int* in_sizes, int n_in,
                              void* d_out, int out_size) {
    const float* x  = (const float*)d_in[0];
    const int*   ei = (const int*)d_in[1];
    const float* ea = (const float*)d_in[2];
    const float* W1 = (const float*)d_in[3];
    const float* b1 = (const float*)d_in[4];
    const float* W2 = (const float*)d_in[5];
    const float* b2 = (const float*)d_in[6];
    const float* W3 = (const float*)d_in[7];
    const float* b3 = (const float*)d_in[8];
    const float* Wc = (const float*)d_in[9];
    const float* bc = (const float*)d_in[10];
    float* out = (float*)d_out;
    int n = in_sizes[0] / 3;
    int e = in_sizes[1] / 2;
    int nb = (n + 511) / 512;

    k_prep<<<87, 256>>>(W1, b1, W2, b2, W3, b3);
    k_zero<<<(n + 255) / 256, 256>>>(n);
    k_count<<<(e + 255) / 256, 256>>>(ei, e);
    k_scan1<<<nb, 512>>>(n);
    k_scan2<<<1, 256>>>(nb);
    k_scan3<<<(n + 255) / 256, 256>>>(n);
    k_fill<<<(e + 255) / 256, 256>>>(ei, e);
    k_agg1<<<(n + 255) / 256, 256>>>(x, ea, n);
    k_l12<<<(n + 1) / 2, 128>>>(x, n);
    k_l23<<<n, 64>>>(n);
    k_l3f<<<(n + 7) / 8, 256>>>(Wc, bc, out, n);
}

// round 7
// speedup vs baseline: 2.1661x; 1.3149x over previous
#include <cuda_runtime.h>

#define N_MAX 50000
#define E_MAX 800000

// ---------------- scratch ----------------
__device__ __align__(16) float g_acc1[N_MAX * 8];    // per node: s1[3], deg, eagg[3], pad
__device__ __align__(16) float g_aj2[N_MAX * 64];
__device__ __align__(16) float g_c2[N_MAX * 64];
__device__ __align__(16) float g_aj3[N_MAX * 32];
__device__ __align__(16) float g_c3[N_MAX * 32];

// CSR
__device__ int  g_cnt[N_MAX];
__device__ int  g_off[N_MAX + 1];
__device__ int  g_cur[N_MAX];
__device__ int  g_part[256];
__device__ int2 g_csr[E_MAX];

// weights
__device__ float g_W1t[10 * 128];                    // rows: Wi(3), Wj(3), We(3), b
// pair-packed: float4 at [k2*64+o] = {Wi(2k2,o), Wj(2k2,o), Wi(2k2+1,o), Wj(2k2+1,o)}
__device__ __align__(16) float g_W2p[64 * 64 * 4];
__device__ float g_W2eb[4 * 64];                     // rows: We(3), b
__device__ __align__(16) float g_W3p[32 * 32 * 4];   // same pairing, k2<32, o<32
__device__ float g_W3eb[4 * 32];

__device__ __forceinline__ void fma2(unsigned long long& acc, unsigned long long h,
                                     unsigned long long w) {
    asm("fma.rn.f32x2 %0, %1, %2, %0;" : "+l"(acc) : "l"(h), "l"(w));
}

// ---------------- weight prep + cnt zero ----------------
__global__ void k_prep(const float* __restrict__ W1, const float* __restrict__ b1,
                       const float* __restrict__ W2, const float* __restrict__ b2,
                       const float* __restrict__ W3, const float* __restrict__ b3, int n) {
    int idx = blockIdx.x * blockDim.x + threadIdx.x;
    if (idx < 1280) {
        int k = idx / 128, o = idx % 128;
        g_W1t[idx] = (k < 9) ? W1[o * 9 + k] : b1[o];
        return;
    }
    idx -= 1280;
    if (idx < 16384) {                               // W2 pair-packed
        int c = idx & 3, o = (idx >> 2) & 63, k2 = idx >> 8;
        g_W2p[idx] = W2[o * 259 + (c & 1) * 128 + 2 * k2 + (c >> 1)];
        return;
    }
    idx -= 16384;
    if (idx < 256) {
        int k = idx / 64, o = idx % 64;
        g_W2eb[idx] = (k < 3) ? W2[o * 259 + 256 + k] : b2[o];
        return;
    }
    idx -= 256;
    if (idx < 4096) {                                // W3 pair-packed
        int c = idx & 3, o = (idx >> 2) & 31, k2 = idx >> 7;
        g_W3p[idx] = W3[o * 131 + (c & 1) * 64 + 2 * k2 + (c >> 1)];
        return;
    }
    idx -= 4096;
    if (idx < 128) {
        int k = idx / 32, o = idx % 32;
        g_W3eb[idx] = (k < 3) ? W3[o * 131 + 128 + k] : b3[o];
        return;
    }
    idx -= 128;
    if (idx < n) g_cnt[idx] = 0;
}

// ---------------- CSR build ----------------
__global__ void k_count(const int* __restrict__ ei, int e) {
    int t = blockIdx.x * blockDim.x + threadIdx.x;
    if (t < e) atomicAdd(&g_cnt[ei[e + t]], 1);
}

__global__ void k_scan1(int n) {
    __shared__ int ws[16];
    int tid = threadIdx.x, lane = tid & 31, wid = tid >> 5;
    int i = blockIdx.x * 512 + tid;
    int s = (i < n) ? g_cnt[i] : 0;
#pragma unroll
    for (int of = 1; of < 32; of <<= 1) {
        int t = __shfl_up_sync(0xffffffffu, s, of);
        if (lane >= of) s += t;
    }
    if (lane == 31) ws[wid] = s;
    __syncthreads();
    if (wid == 0) {
        int v = (lane < 16) ? ws[lane] : 0;
        int ss = v;
#pragma unroll
        for (int of = 1; of < 16; of <<= 1) {
            int t = __shfl_up_sync(0xffffffffu, ss, of);
            if (lane >= of) ss += t;
        }
        if (lane < 16) ws[lane] = ss;
    }
    __syncthreads();
    if (wid) s += ws[wid - 1];
    if (i < n) g_off[i + 1] = s;
    if (tid == 511) g_part[blockIdx.x] = s;
}

__global__ void k_scan2(int nb) {
    __shared__ int sd[256];
    int tid = threadIdx.x;
    int v = (tid < nb) ? g_part[tid] : 0;
    sd[tid] = v;
    __syncthreads();
    for (int of = 1; of < 256; of <<= 1) {
        int t = (tid >= of) ? sd[tid - of] : 0;
        __syncthreads();
        sd[tid] += t;
        __syncthreads();
    }
    if (tid < nb) g_part[tid] = sd[tid] - v;
}

__global__ void k_scan3(int n) {
    int i = blockIdx.x * blockDim.x + threadIdx.x;
    if (i >= n) return;
    int fin = g_off[i + 1] + g_part[i >> 9];
    g_off[i + 1] = fin;
    g_cur[i] = fin - g_cnt[i];
    if (i == 0) g_off[0] = 0;
}

__global__ void k_fill(const int* __restrict__ ei, int e) {
    int t = blockIdx.x * blockDim.x + threadIdx.x;
    if (t >= e) return;
    int s = ei[t], d = ei[e + t];
    int pos = atomicAdd(&g_cur[d], 1);
    g_csr[pos] = make_int2(s, t);
}

// ---------------- layer-1 aggregation (gather) ----------------
__global__ void k_agg1(const float* __restrict__ x, const float* __restrict__ ea, int n) {
    int i = blockIdx.x * blockDim.x + threadIdx.x;
    if (i >= n) return;
    int beg = g_off[i], end = g_off[i + 1];
    float s0 = x[i * 3], s1 = x[i * 3 + 1], s2 = x[i * 3 + 2];
    float e0 = 0.f, e1 = 0.f, e2 = 0.f;
    float t0 = 0.f, t1 = 0.f, t2 = 0.f, f0 = 0.f, f1 = 0.f, f2 = 0.f;
    int j = beg;
    for (; j + 2 <= end; j += 2) {
        int2 a = g_csr[j], b = g_csr[j + 1];
        s0 += x[a.x * 3];     s1 += x[a.x * 3 + 1]; s2 += x[a.x * 3 + 2];
        t0 += x[b.x * 3];     t1 += x[b.x * 3 + 1]; t2 += x[b.x * 3 + 2];
        e0 += ea[a.y * 3];    e1 += ea[a.y * 3 + 1]; e2 += ea[a.y * 3 + 2];
        f0 += ea[b.y * 3];    f1 += ea[b.y * 3 + 1]; f2 += ea[b.y * 3 + 2];
    }
    for (; j < end; j++) {
        int2 a = g_csr[j];
        s0 += x[a.x * 3];  s1 += x[a.x * 3 + 1];  s2 += x[a.x * 3 + 2];
        e0 += ea[a.y * 3]; e1 += ea[a.y * 3 + 1]; e2 += ea[a.y * 3 + 2];
    }
    float4* a = (float4*)g_acc1;
    a[i * 2]     = make_float4(s0 + t0, s1 + t1, s2 + t2, (float)(end - beg + 1));
    a[i * 2 + 1] = make_float4(e0 + f0, e1 + f1, e2 + f2, 0.f);
}

// ---------------- fused layer1 + layer2 transform, blocked GEMM ----------------
// 8 nodes/block, 128 threads. Warp w covers k2 in [w*16, w*16+16); lane covers
// o = lane and lane+32. Pair-packed FFMA2 computes (ai,aj) together.
__global__ void __launch_bounds__(128) k_l12(const float* __restrict__ x, int n) {
    __shared__ float mm[8][8];
    __shared__ float sxs[8][3];
    __shared__ __align__(16) float2 hs[8][128];      // (h,h) packed
    __shared__ __align__(16) float2 ps[4][8][64];    // per-warp partial (ai,aj)
    int t = threadIdx.x;
    int base = blockIdx.x * 8;

    if (t < 64) {
        int nd = t >> 3, c = t & 7;
        if (base + nd < n) mm[nd][c] = g_acc1[(base + nd) * 8 + c];
    } else if (t < 88) {
        int q = t - 64, nd = q / 3, c = q % 3;
        if (base + nd < n) sxs[nd][c] = x[(base + nd) * 3 + c];
    }
    __syncthreads();

    // phase A: h1 for 8 nodes (each thread 8 of 1024 outputs)
    {
        int nd = t >> 4, r = t & 15;
        bool ok = (base + nd < n);
#pragma unroll
        for (int p = 0; p < 8; p++) {
            int oo = r + p * 16;
            float h = 0.f;
            if (ok) {
                float ai = g_W1t[9 * 128 + oo]
                         + sxs[nd][0] * g_W1t[oo] + sxs[nd][1] * g_W1t[128 + oo]
                         + sxs[nd][2] * g_W1t[256 + oo];
                float rr = mm[nd][3] * ai
                         + mm[nd][0] * g_W1t[384 + oo] + mm[nd][1] * g_W1t[512 + oo]
                         + mm[nd][2] * g_W1t[640 + oo]
                         + mm[nd][4] * g_W1t[768 + oo] + mm[nd][5] * g_W1t[896 + oo]
                         + mm[nd][6] * g_W1t[1024 + oo];
                h = fmaxf(rr, 0.0f);
            }
            hs[nd][oo] = make_float2(h, h);
        }
    }
    __syncthreads();

    // phase B: k-split GEMM
    {
        int w = t >> 5, lane = t & 31;
        unsigned long long a0[8], a1[8];
#pragma unroll
        for (int nd = 0; nd < 8; nd++) { a0[nd] = 0ull; a1[nd] = 0ull; }
        const ulonglong2* Wp = (const ulonglong2*)g_W2p;
        const unsigned long long* hsu = (const unsigned long long*)hs;
        int k2b = w * 16;
#pragma unroll 4
        for (int kk = 0; kk < 16; kk++) {
            int k2 = k2b + kk;
            ulonglong2 wa = Wp[k2 * 64 + lane];
            ulonglong2 wb = Wp[k2 * 64 + 32 + lane];
#pragma unroll
            for (int nd = 0; nd < 8; nd++) {
                unsigned long long hp0 = hsu[nd * 128 + 2 * k2];
                unsigned long long hp1 = hsu[nd * 128 + 2 * k2 + 1];
                fma2(a0[nd], hp0, wa.x);
                fma2(a0[nd], hp1, wa.y);
                fma2(a1[nd], hp0, wb.x);
                fma2(a1[nd], hp1, wb.y);
            }
        }
        unsigned long long* psu = (unsigned long long*)ps;
#pragma unroll
        for (int nd = 0; nd < 8; nd++) {
            psu[(w * 8 + nd) * 64 + lane]      = a0[nd];
            psu[(w * 8 + nd) * 64 + lane + 32] = a1[nd];
        }
    }
    __syncthreads();

    // reduce 4 warp-partials, add c-terms, write out
    const float2* psf = (const float2*)ps;
#pragma unroll
    for (int q = 0; q < 4; q++) {
        int pi = t + 128 * q;                        // 0..511
        int nd = pi >> 6, o = pi & 63;
        int i = base + nd;
        if (i >= n) continue;
        float2 p0 = psf[(0 * 8 + nd) * 64 + o];
        float2 p1 = psf[(1 * 8 + nd) * 64 + o];
        float2 p2 = psf[(2 * 8 + nd) * 64 + o];
        float2 p3 = psf[(3 * 8 + nd) * 64 + o];
        float ai = p0.x + p1.x + p2.x + p3.x;
        float aj = p0.y + p1.y + p2.y + p3.y;
        float deg = mm[nd][3];
        float c = deg * (ai + g_W2eb[192 + o]) + aj;
        c += mm[nd][4] * g_W2eb[o] + mm[nd][5] * g_W2eb[64 + o] + mm[nd][6] * g_W2eb[128 + o];
        g_c2[i * 64 + o] = c;
        g_aj2[i * 64 + o] = aj;
    }
}

// ---------------- fused layer2 aggregation + layer3 transform ----------------
__global__ void __launch_bounds__(64) k_l23(int n) {
    __shared__ __align__(16) float2 hs2[64];
    __shared__ float2 pp[2][32];
    __shared__ float mm8[8];
    __shared__ int rng[2];
    int i = blockIdx.x;
    int t = threadIdx.x;

    if (t < 8) mm8[t] = g_acc1[i * 8 + t];
    if (t >= 8 && t < 10) rng[t - 8] = g_off[i + (t - 8)];
    float acc = g_c2[i * 64 + t];
    __syncthreads();

    int beg = rng[0], end = rng[1];
    const int* csx = (const int*)g_csr;
    float a1v = 0.f, a2v = 0.f, a3v = 0.f;
    int j = beg;
    for (; j + 4 <= end; j += 4) {
        int s0 = csx[2 * j], s1 = csx[2 * j + 2], s2 = csx[2 * j + 4], s3 = csx[2 * j + 6];
        acc += g_aj2[s0 * 64 + t];
        a1v += g_aj2[s1 * 64 + t];
        a2v += g_aj2[s2 * 64 + t];
        a3v += g_aj2[s3 * 64 + t];
    }
    for (; j < end; j++) acc += g_aj2[csx[2 * j] * 64 + t];
    float h = fmaxf(acc + a1v + a2v + a3v, 0.0f);
    hs2[t] = make_float2(h, h);
    __syncthreads();

    // transform: warps split k (0..31 / 32..63), packed (ai,aj)
    int w = t >> 5, o = t & 31;
    const ulonglong2* Wp = (const ulonglong2*)g_W3p;
    const unsigned long long* hsu = (const unsigned long long*)hs2;
    unsigned long long a = 0ull;
    int k2b = w * 16;
#pragma unroll
    for (int kk = 0; kk < 16; kk++) {
        int k2 = k2b + kk;
        ulonglong2 wv = Wp[k2 * 32 + o];
        fma2(a, hsu[2 * k2], wv.x);
        fma2(a, hsu[2 * k2 + 1], wv.y);
    }
    ((unsigned long long*)pp)[w * 32 + o] = a;
    __syncthreads();
    if (t < 32) {
        float2 p0 = pp[0][t], p1 = pp[1][t];
        float ai = p0.x + p1.x;
        float aj = p0.y + p1.y;
        float deg = mm8[3];
        float c = deg * (ai + g_W3eb[96 + t]) + aj;
        c += mm8[4] * g_W3eb[t] + mm8[5] * g_W3eb[32 + t] + mm8[6] * g_W3eb[64 + t];
        g_c3[i * 32 + t] = c;
        g_aj3[i * 32 + t] = aj;
    }
}

// ---------------- fused layer3 aggregation + classifier + log_softmax ----------------
__global__ void k_l3f(const float* __restrict__ Wc, const float* __restrict__ bc,
                      float* __restrict__ out, int n) {
    int lane = threadIdx.x & 31;
    int w = threadIdx.x >> 5;
    int i = blockIdx.x * 8 + w;
    if (i >= n) return;

    int beg = g_off[i], end = g_off[i + 1];
    const int* csx = (const int*)g_csr;
    float h = g_c3[i * 32 + lane];
    float h1v = 0.f, h2v = 0.f, h3v = 0.f;
    int j = beg;
    for (; j + 4 <= end; j += 4) {
        int s0 = csx[2 * j], s1 = csx[2 * j + 2], s2 = csx[2 * j + 4], s3 = csx[2 * j + 6];
        h   += g_aj3[s0 * 32 + lane];
        h1v += g_aj3[s1 * 32 + lane];
        h2v += g_aj3[s2 * 32 + lane];
        h3v += g_aj3[s3 * 32 + lane];
    }
    for (; j < end; j++) h += g_aj3[csx[2 * j] * 32 + lane];
    h += h1v + h2v + h3v;

    float l[4];
#pragma unroll
    for (int c = 0; c < 4; c++) {
        float v = h * Wc[c * 32 + lane];
#pragma unroll
        for (int off = 16; off; off >>= 1) v += __shfl_xor_sync(0xffffffff, v, off);
        l[c] = v + bc[c];
    }
    float mx = fmaxf(fmaxf(l[0], l[1]), fmaxf(l[2], l[3]));
    float se = expf(l[0] - mx) + expf(l[1] - mx) + expf(l[2] - mx) + expf(l[3] - mx);
    float lse = mx + logf(se);
    if (lane < 4) out[i * 4 + lane] = l[lane] - lse;
}

extern "C" void kernel_launch(void* const* d_in, const int* in_sizes, int n_in,
                              void* d_out, int out_size) {
    const float* x  = (const float*)d_in[0];
    const int*   ei = (const int*)d_in[1];
    const float* ea = (const float*)d_in[2];
    const float* W1 = (const float*)d_in[3];
    const float* b1 = (const float*)d_in[4];
    const float* W2 = (const float*)d_in[5];
    const float* b2 = (const float*)d_in[6];
    const float* W3 = (const float*)d_in[7];
    const float* b3 = (const float*)d_in[8];
    const float* Wc = (const float*)d_in[9];
    const float* bc = (const float*)d_in[10];
    float* out = (float*)d_out;
    int n = in_sizes[0] / 3;
    int e = in_sizes[1] / 2;
    int nb = (n + 511) / 512;

    k_prep<<<(22144 + n + 255) / 256, 256>>>(W1, b1, W2, b2, W3, b3, n);
    k_count<<<(e + 255) / 256, 256>>>(ei, e);
    k_scan1<<<nb, 512>>>(n);
    k_scan2<<<1, 256>>>(nb);
    k_scan3<<<(n + 255) / 256, 256>>>(n);
    k_fill<<<(e + 255) / 256, 256>>>(ei, e);
    k_agg1<<<(n + 255) / 256, 256>>>(x, ea, n);
    k_l12<<<(n + 7) / 8, 128>>>(x, n);
    k_l23<<<n, 64>>>(n);
    k_l3f<<<(n + 7) / 8, 256>>>(Wc, bc, out, n);
}

// round 9
// speedup vs baseline: 2.2754x; 1.0505x over previous
#include <cuda_runtime.h>
#include <string.h>

#define N_MAX 50000
#define E_MAX 800000

// ---------------- scratch ----------------
__device__ __align__(16) float g_acc1[N_MAX * 8];    // per node: s1[3], deg, eagg[3], pad
__device__ __align__(16) float g_aj2[N_MAX * 64];
__device__ __align__(16) float g_c2[N_MAX * 64];
__device__ __align__(16) float g_aj3[N_MAX * 32];
__device__ __align__(16) float g_c3[N_MAX * 32];

// CSR
__device__ int  g_cnt[N_MAX];
__device__ int  g_off[N_MAX + 1];
__device__ int  g_cur[N_MAX];
__device__ unsigned long long g_desc[128];           // decoupled-lookback tile descriptors
__device__ int2 g_csr[E_MAX];

// weights
__device__ float g_W1t[10 * 128];                    // rows: Wi(3), Wj(3), We(3), b
// pair-packed: float4 at [k2*64+o] = {Wi(2k2,o), Wj(2k2,o), Wi(2k2+1,o), Wj(2k2+1,o)}
__device__ __align__(16) float g_W2p[64 * 64 * 4];
__device__ float g_W2eb[4 * 64];                     // rows: We(3), b
__device__ __align__(16) float g_W3p[32 * 32 * 4];   // same pairing, k2<32, o<32
__device__ float g_W3eb[4 * 32];

__device__ __forceinline__ void fma2(unsigned long long& acc, unsigned long long h,
                                     unsigned long long w) {
    asm("fma.rn.f32x2 %0, %1, %2, %0;" : "+l"(acc) : "l"(h), "l"(w));
}

__device__ __forceinline__ unsigned long long packdup(float h) {
    float2 f = make_float2(h, h);
    unsigned long long u;
    memcpy(&u, &f, 8);
    return u;
}

// ---------------- weight prep + cnt/desc zero ----------------
__global__ void k_prep(const float* __restrict__ W1, const float* __restrict__ b1,
                       const float* __restrict__ W2, const float* __restrict__ b2,
                       const float* __restrict__ W3, const float* __restrict__ b3, int n) {
    int idx = blockIdx.x * blockDim.x + threadIdx.x;
    if (idx < 1280) {
        int k = idx / 128, o = idx % 128;
        g_W1t[idx] = (k < 9) ? W1[o * 9 + k] : b1[o];
        return;
    }
    idx -= 1280;
    if (idx < 16384) {                               // W2 pair-packed
        int c = idx & 3, o = (idx >> 2) & 63, k2 = idx >> 8;
        g_W2p[idx] = W2[o * 259 + (c & 1) * 128 + 2 * k2 + (c >> 1)];
        return;
    }
    idx -= 16384;
    if (idx < 256) {
        int k = idx / 64, o = idx % 64;
        g_W2eb[idx] = (k < 3) ? W2[o * 259 + 256 + k] : b2[o];
        return;
    }
    idx -= 256;
    if (idx < 4096) {                                // W3 pair-packed
        int c = idx & 3, o = (idx >> 2) & 31, k2 = idx >> 7;
        g_W3p[idx] = W3[o * 131 + (c & 1) * 64 + 2 * k2 + (c >> 1)];
        return;
    }
    idx -= 4096;
    if (idx < 128) {
        int k = idx / 32, o = idx % 32;
        g_W3eb[idx] = (k < 3) ? W3[o * 131 + 128 + k] : b3[o];
        return;
    }
    idx -= 128;
    if (idx < 128) {                                 // lookback descriptors
        g_desc[idx] = 0ull;
        return;
    }
    idx -= 128;
    if (idx < n) g_cnt[idx] = 0;
}

// ---------------- CSR build ----------------
__global__ void k_count(const int* __restrict__ ei, int e) {
    int t = blockIdx.x * blockDim.x + threadIdx.x;
    if (t < e) atomicAdd(&g_cnt[ei[e + t]], 1);
}

// single-pass scan with decoupled lookback; writes g_off and g_cur
__global__ void k_scanall(int n) {
    __shared__ int ws[16];
    __shared__ int bprefix;
    int tid = threadIdx.x, lane = tid & 31, wid = tid >> 5;
    int tile = blockIdx.x;
    int i = tile * 512 + tid;
    int v = (i < n) ? g_cnt[i] : 0;
    int s = v;
#pragma unroll
    for (int of = 1; of < 32; of <<= 1) {
        int t = __shfl_up_sync(0xffffffffu, s, of);
        if (lane >= of) s += t;
    }
    if (lane == 31) ws[wid] = s;
    __syncthreads();
    if (wid == 0) {
        int vv = (lane < 16) ? ws[lane] : 0;
        int ss = vv;
#pragma unroll
        for (int of = 1; of < 16; of <<= 1) {
            int t = __shfl_up_sync(0xffffffffu, ss, of);
            if (lane >= of) ss += t;
        }
        if (lane < 16) ws[lane] = ss;
    }
    __syncthreads();
    if (wid) s += ws[wid - 1];
    int total = ws[15];

    if (tid == 0) {
        unsigned long long prefix = 0;
        if (tile == 0) {
            atomicExch(&g_desc[0], ((unsigned long long)total << 2) | 2ull);
        } else {
            atomicExch(&g_desc[tile], ((unsigned long long)total << 2) | 1ull);
            int tt = tile - 1;
            while (true) {
                unsigned long long d = atomicAdd(&g_desc[tt], 0ull);
                unsigned int st = (unsigned int)(d & 3ull);
                if (st == 2u) { prefix += d >> 2; break; }
                if (st == 1u) { prefix += d >> 2; tt--; }
            }
            atomicExch(&g_desc[tile],
                       ((prefix + (unsigned long long)total) << 2) | 2ull);
        }
        bprefix = (int)prefix;
    }
    __syncthreads();
    s += bprefix;
    if (i < n) {
        g_off[i + 1] = s;
        g_cur[i] = s - v;                            // start offset
    }
    if (i == 0) g_off[0] = 0;
}

__global__ void k_fill(const int* __restrict__ ei, int e) {
    int t = blockIdx.x * blockDim.x + threadIdx.x;
    if (t >= e) return;
    int s = ei[t], d = ei[e + t];
    int pos = atomicAdd(&g_cur[d], 1);
    g_csr[pos] = make_int2(s, t);
}

// ---------------- layer-1 aggregation (gather) ----------------
__global__ void k_agg1(const float* __restrict__ x, const float* __restrict__ ea, int n) {
    int i = blockIdx.x * blockDim.x + threadIdx.x;
    if (i >= n) return;
    int beg = g_off[i], end = g_off[i + 1];
    float s0 = x[i * 3], s1 = x[i * 3 + 1], s2 = x[i * 3 + 2];
    float e0 = 0.f, e1 = 0.f, e2 = 0.f;
    float t0 = 0.f, t1 = 0.f, t2 = 0.f, f0 = 0.f, f1 = 0.f, f2 = 0.f;
    int j = beg;
    for (; j + 2 <= end; j += 2) {
        int2 a = g_csr[j], b = g_csr[j + 1];
        s0 += x[a.x * 3];     s1 += x[a.x * 3 + 1]; s2 += x[a.x * 3 + 2];
        t0 += x[b.x * 3];     t1 += x[b.x * 3 + 1]; t2 += x[b.x * 3 + 2];
        e0 += ea[a.y * 3];    e1 += ea[a.y * 3 + 1]; e2 += ea[a.y * 3 + 2];
        f0 += ea[b.y * 3];    f1 += ea[b.y * 3 + 1]; f2 += ea[b.y * 3 + 2];
    }
    for (; j < end; j++) {
        int2 a = g_csr[j];
        s0 += x[a.x * 3];  s1 += x[a.x * 3 + 1];  s2 += x[a.x * 3 + 2];
        e0 += ea[a.y * 3]; e1 += ea[a.y * 3 + 1]; e2 += ea[a.y * 3 + 2];
    }
    float4* a = (float4*)g_acc1;
    a[i * 2]     = make_float4(s0 + t0, s1 + t1, s2 + t2, (float)(end - beg + 1));
    a[i * 2 + 1] = make_float4(e0 + f0, e1 + f1, e2 + f2, 0.f);
}

// ---------------- fused layer1 + layer2 transform, blocked GEMM ----------------
__global__ void __launch_bounds__(128) k_l12(const float* __restrict__ x, int n) {
    __shared__ float mm[8][8];
    __shared__ float sxs[8][3];
    __shared__ __align__(16) float2 hs[8][128];      // (h,h) packed
    __shared__ __align__(16) float2 ps[4][8][64];    // per-warp partial (ai,aj)
    int t = threadIdx.x;
    int base = blockIdx.x * 8;

    if (t < 64) {
        int nd = t >> 3, c = t & 7;
        if (base + nd < n) mm[nd][c] = g_acc1[(base + nd) * 8 + c];
    } else if (t < 88) {
        int q = t - 64, nd = q / 3, c = q % 3;
        if (base + nd < n) sxs[nd][c] = x[(base + nd) * 3 + c];
    }
    __syncthreads();

    // phase A: h1 for 8 nodes
    {
        int nd = t >> 4, r = t & 15;
        bool ok = (base + nd < n);
#pragma unroll
        for (int p = 0; p < 8; p++) {
            int oo = r + p * 16;
            float h = 0.f;
            if (ok) {
                float ai = g_W1t[9 * 128 + oo]
                         + sxs[nd][0] * g_W1t[oo] + sxs[nd][1] * g_W1t[128 + oo]
                         + sxs[nd][2] * g_W1t[256 + oo];
                float rr = mm[nd][3] * ai
                         + mm[nd][0] * g_W1t[384 + oo] + mm[nd][1] * g_W1t[512 + oo]
                         + mm[nd][2] * g_W1t[640 + oo]
                         + mm[nd][4] * g_W1t[768 + oo] + mm[nd][5] * g_W1t[896 + oo]
                         + mm[nd][6] * g_W1t[1024 + oo];
                h = fmaxf(rr, 0.0f);
            }
            hs[nd][oo] = make_float2(h, h);
        }
    }
    __syncthreads();

    // phase B: k-split GEMM
    {
        int w = t >> 5, lane = t & 31;
        unsigned long long a0[8], a1[8];
#pragma unroll
        for (int nd = 0; nd < 8; nd++) { a0[nd] = 0ull; a1[nd] = 0ull; }
        const ulonglong2* Wp = (const ulonglong2*)g_W2p;
        const unsigned long long* hsu = (const unsigned long long*)hs;
        int k2b = w * 16;
#pragma unroll 4
        for (int kk = 0; kk < 16; kk++) {
            int k2 = k2b + kk;
            ulonglong2 wa = Wp[k2 * 64 + lane];
            ulonglong2 wb = Wp[k2 * 64 + 32 + lane];
#pragma unroll
            for (int nd = 0; nd < 8; nd++) {
                unsigned long long hp0 = hsu[nd * 128 + 2 * k2];
                unsigned long long hp1 = hsu[nd * 128 + 2 * k2 + 1];
                fma2(a0[nd], hp0, wa.x);
                fma2(a0[nd], hp1, wa.y);
                fma2(a1[nd], hp0, wb.x);
                fma2(a1[nd], hp1, wb.y);
            }
        }
        unsigned long long* psu = (unsigned long long*)ps;
#pragma unroll
        for (int nd = 0; nd < 8; nd++) {
            psu[(w * 8 + nd) * 64 + lane]      = a0[nd];
            psu[(w * 8 + nd) * 64 + lane + 32] = a1[nd];
        }
    }
    __syncthreads();

    const float2* psf = (const float2*)ps;
#pragma unroll
    for (int q = 0; q < 4; q++) {
        int pi = t + 128 * q;
        int nd = pi >> 6, o = pi & 63;
        int i = base + nd;
        if (i >= n) continue;
        float2 p0 = psf[(0 * 8 + nd) * 64 + o];
        float2 p1 = psf[(1 * 8 + nd) * 64 + o];
        float2 p2 = psf[(2 * 8 + nd) * 64 + o];
        float2 p3 = psf[(3 * 8 + nd) * 64 + o];
        float ai = p0.x + p1.x + p2.x + p3.x;
        float aj = p0.y + p1.y + p2.y + p3.y;
        float deg = mm[nd][3];
        float c = deg * (ai + g_W2eb[192 + o]) + aj;
        c += mm[nd][4] * g_W2eb[o] + mm[nd][5] * g_W2eb[64 + o] + mm[nd][6] * g_W2eb[128 + o];
        g_c2[i * 64 + o] = c;
        g_aj2[i * 64 + o] = aj;
    }
}

// ---------------- fused layer2 aggregation + layer3 transform, 16 nodes/block ----------------
__global__ void __launch_bounds__(256) k_l23(int n) {
    __shared__ float mm[16][8];
    __shared__ int offs[17];
    __shared__ __align__(16) unsigned long long hsu[16 * 64];   // (h,h) per column, 8KB
    __shared__ __align__(16) unsigned long long ps[8][16][32];  // per-warp partials, 32KB
    int t = threadIdx.x;
    int base = blockIdx.x * 16;
    int w = t >> 5, lane = t & 31;

    if (t < 128) {
        int nd = t >> 3, c = t & 7;
        int i = base + nd;
        mm[nd][c] = (i < n) ? g_acc1[i * 8 + c] : 0.f;
    } else if (t < 145) {
        int q = t - 128;
        offs[q] = g_off[min(base + q, n)];
    }
    __syncthreads();

    // gather phase: each warp handles nodes (w) and (w+8)
    const int* csx = (const int*)g_csr;
    const float2* ajp = (const float2*)g_aj2;
    const float2* c2p = (const float2*)g_c2;
#pragma unroll
    for (int rep = 0; rep < 2; rep++) {
        int nd = w + rep * 8;
        int i = base + nd;
        if (i < n) {
            float2 acc = c2p[i * 32 + lane];
            float2 a1 = make_float2(0.f, 0.f), a2 = make_float2(0.f, 0.f),
                   a3 = make_float2(0.f, 0.f);
            int beg = offs[nd], end = offs[nd + 1];
            int j = beg;
            for (; j + 4 <= end; j += 4) {
                int s0 = csx[2 * j], s1 = csx[2 * j + 2];
                int s2 = csx[2 * j + 4], s3 = csx[2 * j + 6];
                float2 v0 = ajp[s0 * 32 + lane];
                float2 v1 = ajp[s1 * 32 + lane];
                float2 v2 = ajp[s2 * 32 + lane];
                float2 v3 = ajp[s3 * 32 + lane];
                acc.x += v0.x; acc.y += v0.y;
                a1.x += v1.x;  a1.y += v1.y;
                a2.x += v2.x;  a2.y += v2.y;
                a3.x += v3.x;  a3.y += v3.y;
            }
            for (; j < end; j++) {
                float2 v = ajp[csx[2 * j] * 32 + lane];
                acc.x += v.x; acc.y += v.y;
            }
            float h0 = fmaxf(acc.x + a1.x + a2.x + a3.x, 0.0f);
            float h1 = fmaxf(acc.y + a1.y + a2.y + a3.y, 0.0f);
            hsu[nd * 64 + 2 * lane]     = packdup(h0);
            hsu[nd * 64 + 2 * lane + 1] = packdup(h1);
        } else {
            hsu[nd * 64 + 2 * lane]     = 0ull;
            hsu[nd * 64 + 2 * lane + 1] = 0ull;
        }
    }
    __syncthreads();

    // transform: 8 warps split k2 (4 each), 16 nodes, pair-packed (ai,aj)
    {
        unsigned long long acc[16];
#pragma unroll
        for (int nd = 0; nd < 16; nd++) acc[nd] = 0ull;
        const ulonglong2* Wp = (const ulonglong2*)g_W3p;
        int k2b = w * 4;
#pragma unroll
        for (int kk = 0; kk < 4; kk++) {
            int k2 = k2b + kk;
            ulonglong2 wv = Wp[k2 * 32 + lane];
#pragma unroll
            for (int nd = 0; nd < 16; nd++) {
                fma2(acc[nd], hsu[nd * 64 + 2 * k2], wv.x);
                fma2(acc[nd], hsu[nd * 64 + 2 * k2 + 1], wv.y);
            }
        }
#pragma unroll
        for (int nd = 0; nd < 16; nd++) ps[w][nd][lane] = acc[nd];
    }
    __syncthreads();

    // reduce 8 partials, apply c-terms
#pragma unroll
    for (int rep = 0; rep < 2; rep++) {
        int pi = t + rep * 256;
        int nd = pi >> 5, o = pi & 31;
        int i = base + nd;
        if (i >= n) continue;
        float ai = 0.f, aj = 0.f;
#pragma unroll
        for (int w8 = 0; w8 < 8; w8++) {
            float2 p = *(const float2*)&ps[w8][nd][o];
            ai += p.x; aj += p.y;
        }
        float deg = mm[nd][3];
        float c = deg * (ai + g_W3eb[96 + o]) + aj;
        c += mm[nd][4] * g_W3eb[o] + mm[nd][5] * g_W3eb[32 + o] + mm[nd][6] * g_W3eb[64 + o];
        g_c3[i * 32 + o] = c;
        g_aj3[i * 32 + o] = aj;
    }
}

// ---------------- fused layer3 aggregation + classifier + log_softmax ----------------
__global__ void k_l3f(const float* __restrict__ Wc, const float* __restrict__ bc,
                      float* __restrict__ out, int n) {
    int lane = threadIdx.x & 31;
    int w = threadIdx.x >> 5;
    int i = blockIdx.x * 8 + w;
    if (i >= n) return;

    int beg = g_off[i], end = g_off[i + 1];
    const int* csx = (const int*)g_csr;
    float h = g_c3[i * 32 + lane];
    float h1v = 0.f, h2v = 0.f, h3v = 0.f;
    int j = beg;
    for (; j + 4 <= end; j += 4) {
        int s0 = csx[2 * j], s1 = csx[2 * j + 2], s2 = csx[2 * j + 4], s3 = csx[2 * j + 6];
        h   += g_aj3[s0 * 32 + lane];
        h1v += g_aj3[s1 * 32 + lane];
        h2v += g_aj3[s2 * 32 + lane];
        h3v += g_aj3[s3 * 32 + lane];
    }
    for (; j < end; j++) h += g_aj3[csx[2 * j] * 32 + lane];
    h += h1v + h2v + h3v;

    float l[4];
#pragma unroll
    for (int c = 0; c < 4; c++) {
        float v = h * Wc[c * 32 + lane];
#pragma unroll
        for (int off = 16; off; off >>= 1) v += __shfl_xor_sync(0xffffffff, v, off);
        l[c] = v + bc[c];
    }
    float mx = fmaxf(fmaxf(l[0], l[1]), fmaxf(l[2], l[3]));
    float se = expf(l[0] - mx) + expf(l[1] - mx) + expf(l[2] - mx) + expf(l[3] - mx);
    float lse = mx + logf(se);
    if (lane < 4) out[i * 4 + lane] = l[lane] - lse;
}

extern "C" void kernel_launch(void* const* d_in, const int* in_sizes, int n_in,
                              void* d_out, int out_size) {
    const float* x  = (const float*)d_in[0];
    const int*   ei = (const int*)d_in[1];
    const float* ea = (const float*)d_in[2];
    const float* W1 = (const float*)d_in[3];
    const float* b1 = (const float*)d_in[4];
    const float* W2 = (const float*)d_in[5];
    const float* b2 = (const float*)d_in[6];
    const float* W3 = (const float*)d_in[7];
    const float* b3 = (const float*)d_in[8];
    const float* Wc = (const float*)d_in[9];
    const float* bc = (const float*)d_in[10];
    float* out = (float*)d_out;
    int n = in_sizes[0] / 3;
    int e = in_sizes[1] / 2;
    int nb = (n + 511) / 512;

    k_prep<<<(22272 + n + 255) / 256, 256>>>(W1, b1, W2, b2, W3, b3, n);
    k_count<<<(e + 255) / 256, 256>>>(ei, e);
    k_scanall<<<nb, 512>>>(n);
    k_fill<<<(e + 255) / 256, 256>>>(ei, e);
    k_agg1<<<(n + 255) / 256, 256>>>(x, ea, n);
    k_l12<<<(n + 7) / 8, 128>>>(x, n);
    k_l23<<<(n + 15) / 16, 256>>>(n);
    k_l3f<<<(n + 7) / 8, 256>>>(Wc, bc, out, n);
}

// round 10
// speedup vs baseline: 2.4061x; 1.0574x over previous
#include <cuda_runtime.h>
#include <string.h>

#define N_MAX 50000
#define E_MAX 800000

// ---------------- scratch ----------------
__device__ __align__(16) float g_acc1[N_MAX * 8];    // per node: s1[3], deg, eagg[3], pad
__device__ __align__(16) float g_aj2[N_MAX * 64];
__device__ __align__(16) float g_c2[N_MAX * 64];
__device__ __align__(16) float g_z3[N_MAX * 4];      // c3 @ Wc.T + bc
__device__ __align__(16) float g_y3[N_MAX * 4];      // aj3 @ Wc.T

// CSR
__device__ int  g_cnt[N_MAX];
__device__ int  g_off[N_MAX + 1];
__device__ int  g_cur[N_MAX];
__device__ unsigned long long g_desc[128];           // decoupled-lookback tile descriptors
__device__ int  g_csr[E_MAX];                        // src only, sorted by dst

// weights
__device__ float g_W1t[10 * 128];                    // rows: Wi(3), Wj(3), We(3), b
// pair-packed: float4 at [k2*64+o] = {Wi(2k2,o), Wj(2k2,o), Wi(2k2+1,o), Wj(2k2+1,o)}
__device__ __align__(16) float g_W2p[64 * 64 * 4];
__device__ float g_W2eb[4 * 64];                     // rows: We(3), b
__device__ __align__(16) float g_W3p[32 * 32 * 4];   // same pairing, k2<32, o<32
__device__ float g_W3eb[4 * 32];

__device__ __forceinline__ void fma2(unsigned long long& acc, unsigned long long h,
                                     unsigned long long w) {
    asm("fma.rn.f32x2 %0, %1, %2, %0;" : "+l"(acc) : "l"(h), "l"(w));
}

__device__ __forceinline__ unsigned long long packdup(float h) {
    float2 f = make_float2(h, h);
    unsigned long long u;
    memcpy(&u, &f, 8);
    return u;
}

// ---------------- weight prep + cnt/eagg/desc zero ----------------
__global__ void k_prep(const float* __restrict__ W1, const float* __restrict__ b1,
                       const float* __restrict__ W2, const float* __restrict__ b2,
                       const float* __restrict__ W3, const float* __restrict__ b3, int n) {
    int idx = blockIdx.x * blockDim.x + threadIdx.x;
    if (idx < 1280) {
        int k = idx / 128, o = idx % 128;
        g_W1t[idx] = (k < 9) ? W1[o * 9 + k] : b1[o];
        return;
    }
    idx -= 1280;
    if (idx < 16384) {                               // W2 pair-packed
        int c = idx & 3, o = (idx >> 2) & 63, k2 = idx >> 8;
        g_W2p[idx] = W2[o * 259 + (c & 1) * 128 + 2 * k2 + (c >> 1)];
        return;
    }
    idx -= 16384;
    if (idx < 256) {
        int k = idx / 64, o = idx % 64;
        g_W2eb[idx] = (k < 3) ? W2[o * 259 + 256 + k] : b2[o];
        return;
    }
    idx -= 256;
    if (idx < 4096) {                                // W3 pair-packed
        int c = idx & 3, o = (idx >> 2) & 31, k2 = idx >> 7;
        g_W3p[idx] = W3[o * 131 + (c & 1) * 64 + 2 * k2 + (c >> 1)];
        return;
    }
    idx -= 4096;
    if (idx < 128) {
        int k = idx / 32, o = idx % 32;
        g_W3eb[idx] = (k < 3) ? W3[o * 131 + 128 + k] : b3[o];
        return;
    }
    idx -= 128;
    if (idx < 128) {                                 // lookback descriptors
        g_desc[idx] = 0ull;
        return;
    }
    idx -= 128;
    if (idx < n) {
        g_cnt[idx] = 0;
        ((float4*)g_acc1)[idx * 2 + 1] = make_float4(0.f, 0.f, 0.f, 0.f);  // eagg
    }
}

// ---------------- CSR build ----------------
__global__ void k_count(const int* __restrict__ ei, int e) {
    int t = blockIdx.x * blockDim.x + threadIdx.x;
    if (t < e) atomicAdd(&g_cnt[ei[e + t]], 1);
}

// single-pass scan with decoupled lookback; writes g_off and g_cur
__global__ void k_scanall(int n) {
    __shared__ int ws[16];
    __shared__ int bprefix;
    int tid = threadIdx.x, lane = tid & 31, wid = tid >> 5;
    int tile = blockIdx.x;
    int i = tile * 512 + tid;
    int v = (i < n) ? g_cnt[i] : 0;
    int s = v;
#pragma unroll
    for (int of = 1; of < 32; of <<= 1) {
        int t = __shfl_up_sync(0xffffffffu, s, of);
        if (lane >= of) s += t;
    }
    if (lane == 31) ws[wid] = s;
    __syncthreads();
    if (wid == 0) {
        int vv = (lane < 16) ? ws[lane] : 0;
        int ss = vv;
#pragma unroll
        for (int of = 1; of < 16; of <<= 1) {
            int t = __shfl_up_sync(0xffffffffu, ss, of);
            if (lane >= of) ss += t;
        }
        if (lane < 16) ws[lane] = ss;
    }
    __syncthreads();
    if (wid) s += ws[wid - 1];
    int total = ws[15];

    if (tid == 0) {
        unsigned long long prefix = 0;
        if (tile == 0) {
            atomicExch(&g_desc[0], ((unsigned long long)total << 2) | 2ull);
        } else {
            atomicExch(&g_desc[tile], ((unsigned long long)total << 2) | 1ull);
            int tt = tile - 1;
            while (true) {
                unsigned long long d = atomicAdd(&g_desc[tt], 0ull);
                unsigned int st = (unsigned int)(d & 3ull);
                if (st == 2u) { prefix += d >> 2; break; }
                if (st == 1u) { prefix += d >> 2; tt--; }
            }
            atomicExch(&g_desc[tile],
                       ((prefix + (unsigned long long)total) << 2) | 2ull);
        }
        bprefix = (int)prefix;
    }
    __syncthreads();
    s += bprefix;
    if (i < n) {
        g_off[i + 1] = s;
        g_cur[i] = s - v;                            // start offset
    }
    if (i == 0) g_off[0] = 0;
}

// fill CSR (src only) + accumulate edge_attr into g_acc1 (coalesced ea read)
__global__ void k_fill(const int* __restrict__ ei, const float* __restrict__ ea, int e) {
    int t = blockIdx.x * blockDim.x + threadIdx.x;
    if (t >= e) return;
    int s = ei[t], d = ei[e + t];
    int pos = atomicAdd(&g_cur[d], 1);
    g_csr[pos] = s;
    float e0 = ea[t * 3], e1 = ea[t * 3 + 1], e2 = ea[t * 3 + 2];
    atomicAdd((float4*)&g_acc1[d * 8 + 4], make_float4(e0, e1, e2, 0.f));
}

// ---------------- layer-1 aggregation (x gather only) ----------------
__global__ void k_agg1(const float* __restrict__ x, int n) {
    int i = blockIdx.x * blockDim.x + threadIdx.x;
    if (i >= n) return;
    int beg = g_off[i], end = g_off[i + 1];
    float a0 = x[i * 3], a1 = x[i * 3 + 1], a2 = x[i * 3 + 2];   // self loop
    float b0 = 0.f, b1 = 0.f, b2 = 0.f;
    float c0 = 0.f, c1 = 0.f, c2 = 0.f;
    float d0 = 0.f, d1 = 0.f, d2 = 0.f;
    int j = beg;
    for (; j + 4 <= end; j += 4) {
        int s0 = g_csr[j], s1 = g_csr[j + 1], s2 = g_csr[j + 2], s3 = g_csr[j + 3];
        a0 += x[s0 * 3]; a1 += x[s0 * 3 + 1]; a2 += x[s0 * 3 + 2];
        b0 += x[s1 * 3]; b1 += x[s1 * 3 + 1]; b2 += x[s1 * 3 + 2];
        c0 += x[s2 * 3]; c1 += x[s2 * 3 + 1]; c2 += x[s2 * 3 + 2];
        d0 += x[s3 * 3]; d1 += x[s3 * 3 + 1]; d2 += x[s3 * 3 + 2];
    }
    for (; j < end; j++) {
        int s0 = g_csr[j];
        a0 += x[s0 * 3]; a1 += x[s0 * 3 + 1]; a2 += x[s0 * 3 + 2];
    }
    ((float4*)g_acc1)[i * 2] = make_float4(a0 + b0 + c0 + d0, a1 + b1 + c1 + d1,
                                           a2 + b2 + c2 + d2, (float)(end - beg + 1));
}

// ---------------- fused layer1 + layer2 transform, blocked GEMM ----------------
__global__ void __launch_bounds__(128) k_l12(const float* __restrict__ x, int n) {
    __shared__ float mm[8][8];
    __shared__ float sxs[8][3];
    __shared__ __align__(16) float2 hs[8][128];      // (h,h) packed
    __shared__ __align__(16) float2 ps[4][8][64];    // per-warp partial (ai,aj)
    int t = threadIdx.x;
    int base = blockIdx.x * 8;

    if (t < 64) {
        int nd = t >> 3, c = t & 7;
        if (base + nd < n) mm[nd][c] = g_acc1[(base + nd) * 8 + c];
    } else if (t < 88) {
        int q = t - 64, nd = q / 3, c = q % 3;
        if (base + nd < n) sxs[nd][c] = x[(base + nd) * 3 + c];
    }
    __syncthreads();

    // phase A: h1 for 8 nodes
    {
        int nd = t >> 4, r = t & 15;
        bool ok = (base + nd < n);
#pragma unroll
        for (int p = 0; p < 8; p++) {
            int oo = r + p * 16;
            float h = 0.f;
            if (ok) {
                float ai = g_W1t[9 * 128 + oo]
                         + sxs[nd][0] * g_W1t[oo] + sxs[nd][1] * g_W1t[128 + oo]
                         + sxs[nd][2] * g_W1t[256 + oo];
                float rr = mm[nd][3] * ai
                         + mm[nd][0] * g_W1t[384 + oo] + mm[nd][1] * g_W1t[512 + oo]
                         + mm[nd][2] * g_W1t[640 + oo]
                         + mm[nd][4] * g_W1t[768 + oo] + mm[nd][5] * g_W1t[896 + oo]
                         + mm[nd][6] * g_W1t[1024 + oo];
                h = fmaxf(rr, 0.0f);
            }
            hs[nd][oo] = make_float2(h, h);
        }
    }
    __syncthreads();

    // phase B: k-split GEMM
    {
        int w = t >> 5, lane = t & 31;
        unsigned long long a0[8], a1[8];
#pragma unroll
        for (int nd = 0; nd < 8; nd++) { a0[nd] = 0ull; a1[nd] = 0ull; }
        const ulonglong2* Wp = (const ulonglong2*)g_W2p;
        const unsigned long long* hsu = (const unsigned long long*)hs;
        int k2b = w * 16;
#pragma unroll 4
        for (int kk = 0; kk < 16; kk++) {
            int k2 = k2b + kk;
            ulonglong2 wa = Wp[k2 * 64 + lane];
            ulonglong2 wb = Wp[k2 * 64 + 32 + lane];
#pragma unroll
            for (int nd = 0; nd < 8; nd++) {
                unsigned long long hp0 = hsu[nd * 128 + 2 * k2];
                unsigned long long hp1 = hsu[nd * 128 + 2 * k2 + 1];
                fma2(a0[nd], hp0, wa.x);
                fma2(a0[nd], hp1, wa.y);
                fma2(a1[nd], hp0, wb.x);
                fma2(a1[nd], hp1, wb.y);
            }
        }
        unsigned long long* psu = (unsigned long long*)ps;
#pragma unroll
        for (int nd = 0; nd < 8; nd++) {
            psu[(w * 8 + nd) * 64 + lane]      = a0[nd];
            psu[(w * 8 + nd) * 64 + lane + 32] = a1[nd];
        }
    }
    __syncthreads();

    const float2* psf = (const float2*)ps;
#pragma unroll
    for (int q = 0; q < 4; q++) {
        int pi = t + 128 * q;
        int nd = pi >> 6, o = pi & 63;
        int i = base + nd;
        if (i >= n) continue;
        float2 p0 = psf[(0 * 8 + nd) * 64 + o];
        float2 p1 = psf[(1 * 8 + nd) * 64 + o];
        float2 p2 = psf[(2 * 8 + nd) * 64 + o];
        float2 p3 = psf[(3 * 8 + nd) * 64 + o];
        float ai = p0.x + p1.x + p2.x + p3.x;
        float aj = p0.y + p1.y + p2.y + p3.y;
        float deg = mm[nd][3];
        float c = deg * (ai + g_W2eb[192 + o]) + aj;
        c += mm[nd][4] * g_W2eb[o] + mm[nd][5] * g_W2eb[64 + o] + mm[nd][6] * g_W2eb[128 + o];
        g_c2[i * 64 + o] = c;
        g_aj2[i * 64 + o] = aj;
    }
}

// ---------- fused layer2 agg + layer3 transform + classifier projection ----------
__global__ void __launch_bounds__(256) k_l23(const float* __restrict__ Wc,
                                             const float* __restrict__ bc, int n) {
    __shared__ float mm[16][8];
    __shared__ int offs[17];
    __shared__ __align__(16) unsigned long long hsu[16 * 64];   // (h,h) per column, 8KB
    __shared__ __align__(16) unsigned long long ps[8][16][32];  // per-warp partials, 32KB
    __shared__ float c3s[16][33];
    __shared__ float aj3s[16][33];
    __shared__ float wcs[128];
    __shared__ float bcs[4];
    int t = threadIdx.x;
    int base = blockIdx.x * 16;
    int w = t >> 5, lane = t & 31;

    if (t < 128) {
        int nd = t >> 3, c = t & 7;
        int i = base + nd;
        mm[nd][c] = (i < n) ? g_acc1[i * 8 + c] : 0.f;
    } else {
        wcs[t - 128] = Wc[t - 128];
    }
    if (t < 17) offs[t] = g_off[min(base + t, n)];
    if (t >= 20 && t < 24) bcs[t - 20] = bc[t - 20];
    __syncthreads();

    // gather phase: each warp handles nodes (w) and (w+8)
    const float2* ajp = (const float2*)g_aj2;
    const float2* c2p = (const float2*)g_c2;
#pragma unroll
    for (int rep = 0; rep < 2; rep++) {
        int nd = w + rep * 8;
        int i = base + nd;
        if (i < n) {
            float2 acc = c2p[i * 32 + lane];
            float2 a1 = make_float2(0.f, 0.f), a2 = make_float2(0.f, 0.f),
                   a3 = make_float2(0.f, 0.f);
            int beg = offs[nd], end = offs[nd + 1];
            int j = beg;
            for (; j + 4 <= end; j += 4) {
                int s0 = g_csr[j], s1 = g_csr[j + 1];
                int s2 = g_csr[j + 2], s3 = g_csr[j + 3];
                float2 v0 = ajp[s0 * 32 + lane];
                float2 v1 = ajp[s1 * 32 + lane];
                float2 v2 = ajp[s2 * 32 + lane];
                float2 v3 = ajp[s3 * 32 + lane];
                acc.x += v0.x; acc.y += v0.y;
                a1.x += v1.x;  a1.y += v1.y;
                a2.x += v2.x;  a2.y += v2.y;
                a3.x += v3.x;  a3.y += v3.y;
            }
            for (; j < end; j++) {
                float2 v = ajp[g_csr[j] * 32 + lane];
                acc.x += v.x; acc.y += v.y;
            }
            float h0 = fmaxf(acc.x + a1.x + a2.x + a3.x, 0.0f);
            float h1 = fmaxf(acc.y + a1.y + a2.y + a3.y, 0.0f);
            hsu[nd * 64 + 2 * lane]     = packdup(h0);
            hsu[nd * 64 + 2 * lane + 1] = packdup(h1);
        } else {
            hsu[nd * 64 + 2 * lane]     = 0ull;
            hsu[nd * 64 + 2 * lane + 1] = 0ull;
        }
    }
    __syncthreads();

    // transform: 8 warps split k2 (4 each), 16 nodes, pair-packed (ai,aj)
    {
        unsigned long long acc[16];
#pragma unroll
        for (int nd = 0; nd < 16; nd++) acc[nd] = 0ull;
        const ulonglong2* Wp = (const ulonglong2*)g_W3p;
        int k2b = w * 4;
#pragma unroll
        for (int kk = 0; kk < 4; kk++) {
            int k2 = k2b + kk;
            ulonglong2 wv = Wp[k2 * 32 + lane];
#pragma unroll
            for (int nd = 0; nd < 16; nd++) {
                fma2(acc[nd], hsu[nd * 64 + 2 * k2], wv.x);
                fma2(acc[nd], hsu[nd * 64 + 2 * k2 + 1], wv.y);
            }
        }
#pragma unroll
        for (int nd = 0; nd < 16; nd++) ps[w][nd][lane] = acc[nd];
    }
    __syncthreads();

    // reduce 8 partials, apply c-terms -> c3s / aj3s in smem
#pragma unroll
    for (int rep = 0; rep < 2; rep++) {
        int pi = t + rep * 256;
        int nd = pi >> 5, o = pi & 31;
        int i = base + nd;
        if (i >= n) continue;
        float ai = 0.f, aj = 0.f;
#pragma unroll
        for (int w8 = 0; w8 < 8; w8++) {
            float2 p = *(const float2*)&ps[w8][nd][o];
            ai += p.x; aj += p.y;
        }
        float deg = mm[nd][3];
        float c = deg * (ai + g_W3eb[96 + o]) + aj;
        c += mm[nd][4] * g_W3eb[o] + mm[nd][5] * g_W3eb[32 + o] + mm[nd][6] * g_W3eb[64 + o];
        c3s[nd][o] = c;
        aj3s[nd][o] = aj;
    }
    __syncthreads();

    // classifier projection: z3 = c3@Wc.T + bc, y3 = aj3@Wc.T
    if (t < 128) {
        int q = t & 63;
        int nd = q >> 2, c = q & 3;
        int i = base + nd;
        if (i < n) {
            const float* src = (t < 64) ? c3s[nd] : aj3s[nd];
            float acc = (t < 64) ? bcs[c] : 0.f;
#pragma unroll 8
            for (int o = 0; o < 32; o++) acc += src[o] * wcs[c * 32 + o];
            if (t < 64) g_z3[i * 4 + c] = acc;
            else        g_y3[i * 4 + c] = acc;
        }
    }
}

// ---------------- layer3 agg in logit space + log_softmax ----------------
__global__ void k_l3f(float* __restrict__ out, int n) {
    int i = blockIdx.x * blockDim.x + threadIdx.x;
    if (i >= n) return;
    const float4* y = (const float4*)g_y3;
    float4 l = ((const float4*)g_z3)[i];
    float4 A = make_float4(0.f, 0.f, 0.f, 0.f), B = A, C = A, D = A;
    int beg = g_off[i], end = g_off[i + 1];
    int j = beg;
    for (; j + 4 <= end; j += 4) {
        int s0 = g_csr[j], s1 = g_csr[j + 1], s2 = g_csr[j + 2], s3 = g_csr[j + 3];
        float4 v0 = y[s0], v1 = y[s1], v2 = y[s2], v3 = y[s3];
        A.x += v0.x; A.y += v0.y; A.z += v0.z; A.w += v0.w;
        B.x += v1.x; B.y += v1.y; B.z += v1.z; B.w += v1.w;
        C.x += v2.x; C.y += v2.y; C.z += v2.z; C.w += v2.w;
        D.x += v3.x; D.y += v3.y; D.z += v3.z; D.w += v3.w;
    }
    for (; j < end; j++) {
        float4 v = y[g_csr[j]];
        A.x += v.x; A.y += v.y; A.z += v.z; A.w += v.w;
    }
    l.x += A.x + B.x + C.x + D.x;
    l.y += A.y + B.y + C.y + D.y;
    l.z += A.z + B.z + C.z + D.z;
    l.w += A.w + B.w + C.w + D.w;

    float mx = fmaxf(fmaxf(l.x, l.y), fmaxf(l.z, l.w));
    float se = expf(l.x - mx) + expf(l.y - mx) + expf(l.z - mx) + expf(l.w - mx);
    float lse = mx + logf(se);
    ((float4*)out)[i] = make_float4(l.x - lse, l.y - lse, l.z - lse, l.w - lse);
}

extern "C" void kernel_launch(void* const* d_in, const int* in_sizes, int n_in,
                              void* d_out, int out_size) {
    const float* x  = (const float*)d_in[0];
    const int*   ei = (const int*)d_in[1];
    const float* ea = (const float*)d_in[2];
    const float* W1 = (const float*)d_in[3];
    const float* b1 = (const float*)d_in[4];
    const float* W2 = (const float*)d_in[5];
    const float* b2 = (const float*)d_in[6];
    const float* W3 = (const float*)d_in[7];
    const float* b3 = (const float*)d_in[8];
    const float* Wc = (const float*)d_in[9];
    const float* bc = (const float*)d_in[10];
    float* out = (float*)d_out;
    int n = in_sizes[0] / 3;
    int e = in_sizes[1] / 2;
    int nb = (n + 511) / 512;

    k_prep<<<(22272 + n + 255) / 256, 256>>>(W1, b1, W2, b2, W3, b3, n);
    k_count<<<(e + 255) / 256, 256>>>(ei, e);
    k_scanall<<<nb, 512>>>(n);
    k_fill<<<(e + 255) / 256, 256>>>(ei, ea, e);
    k_agg1<<<(n + 255) / 256, 256>>>(x, n);
    k_l12<<<(n + 7) / 8, 128>>>(x, n);
    k_l23<<<(n + 15) / 16, 256>>>(Wc, bc, n);
    k_l3f<<<(n + 255) / 256, 256>>>(out, n);
}